// round 3
// baseline (speedup 1.0000x reference)
#include <cuda_runtime.h>
#include <cuda_bf16.h>
#include <cstdint>

#define NVERT   16384
#define QCOLS   4096                 // columns per quarter
#define NUNITS  32768                // 8192 row-pairs * 4 column-quarters
#define BLOCK   1024
#define MAXGRID 512
#define SMEM_BYTES (3 * NVERT * sizeof(float))   // 196608 B

// Deterministic partial sums: y4[q][row][comp]
__device__ float g_y4[4 * NVERT * 3];
// Per-block loss partials (fixed slice per block -> deterministic)
__device__ float g_part[MAXGRID];
// Work-stealing + barrier state (reset by block 0 at end of each run)
__device__ unsigned int g_ticket = 0;
__device__ unsigned int g_bar1   = 0;
__device__ unsigned int g_bar2   = 0;

__device__ __forceinline__ float block_reduce(float s, float* red) {
    const int lane = threadIdx.x & 31;
    const int wid  = threadIdx.x >> 5;
    #pragma unroll
    for (int off = 16; off > 0; off >>= 1)
        s += __shfl_xor_sync(0xFFFFFFFFu, s, off);
    if (lane == 0) red[wid] = s;
    __syncthreads();
    float t = 0.f;
    if (wid == 0) {
        t = (lane < (BLOCK >> 5)) ? red[lane] : 0.f;
        #pragma unroll
        for (int off = 16; off > 0; off >>= 1)
            t += __shfl_xor_sync(0xFFFFFFFFu, t, off);
    }
    return t;   // valid in warp 0
}

__global__ void __launch_bounds__(BLOCK, 1)
lap_fused_kernel(const float* __restrict__ L, const float* __restrict__ x,
                 float* __restrict__ out) {
    extern __shared__ float sx[];   // SoA: [3][NVERT]
    __shared__ float red[32];

    // Stage x into shared memory: SoA, per-vertex
    for (int vert = threadIdx.x; vert < NVERT; vert += BLOCK) {
        float a = x[3 * vert + 0];
        float b = x[3 * vert + 1];
        float c = x[3 * vert + 2];
        sx[0 * NVERT + vert] = a;
        sx[1 * NVERT + vert] = b;
        sx[2 * NVERT + vert] = c;
    }
    __syncthreads();

    const int lane = threadIdx.x & 31;

    // ---------------- Phase 1: stream L with work stealing ----------------
    for (;;) {
        unsigned int u;
        if (lane == 0) u = atomicAdd(&g_ticket, 1u);
        u = __shfl_sync(0xFFFFFFFFu, u, 0);
        if (u >= NUNITS) break;

        const int p = (int)(u >> 2);   // row pair -> rows 2p, 2p+1
        const int q = (int)(u & 3);    // column quarter

        const float4* __restrict__ r0 =
            (const float4*)(L + (size_t)(2 * p) * NVERT + q * QCOLS);
        const float4* __restrict__ r1 = r0 + (NVERT / 4);

        const float4* __restrict__ xs0 = (const float4*)(sx + 0 * NVERT + q * QCOLS);
        const float4* __restrict__ xs1 = (const float4*)(sx + 1 * NVERT + q * QCOLS);
        const float4* __restrict__ xs2 = (const float4*)(sx + 2 * NVERT + q * QCOLS);

        float a00 = 0.f, a01 = 0.f, a02 = 0.f;
        float a10 = 0.f, a11 = 0.f, a12 = 0.f;

        #pragma unroll 4
        for (int i = lane; i < QCOLS / 4; i += 32) {
            float4 l0 = __ldcs(r0 + i);   // streaming: L has zero reuse
            float4 l1 = __ldcs(r1 + i);
            float4 v0 = xs0[i];
            float4 v1 = xs1[i];
            float4 v2 = xs2[i];

            a00 += l0.x * v0.x + l0.y * v0.y + l0.z * v0.z + l0.w * v0.w;
            a01 += l0.x * v1.x + l0.y * v1.y + l0.z * v1.z + l0.w * v1.w;
            a02 += l0.x * v2.x + l0.y * v2.y + l0.z * v2.z + l0.w * v2.w;
            a10 += l1.x * v0.x + l1.y * v0.y + l1.z * v0.z + l1.w * v0.w;
            a11 += l1.x * v1.x + l1.y * v1.y + l1.z * v1.z + l1.w * v1.w;
            a12 += l1.x * v2.x + l1.y * v2.y + l1.z * v2.z + l1.w * v2.w;
        }

        #pragma unroll
        for (int off = 16; off > 0; off >>= 1) {
            a00 += __shfl_xor_sync(0xFFFFFFFFu, a00, off);
            a01 += __shfl_xor_sync(0xFFFFFFFFu, a01, off);
            a02 += __shfl_xor_sync(0xFFFFFFFFu, a02, off);
            a10 += __shfl_xor_sync(0xFFFFFFFFu, a10, off);
            a11 += __shfl_xor_sync(0xFFFFFFFFu, a11, off);
            a12 += __shfl_xor_sync(0xFFFFFFFFu, a12, off);
        }

        if (lane < 6) {
            float v;
            switch (lane) {
                case 0: v = a00; break;
                case 1: v = a01; break;
                case 2: v = a02; break;
                case 3: v = a10; break;
                case 4: v = a11; break;
                default: v = a12; break;
            }
            const int row = 2 * p + (lane >= 3 ? 1 : 0);
            const int c   = (lane >= 3) ? (lane - 3) : lane;
            g_y4[(q * NVERT + row) * 3 + c] = v;
        }
    }

    // ---------------- Grid barrier 1 (all blocks co-resident: grid == #SMs) ----
    __syncthreads();
    if (threadIdx.x == 0) {
        __threadfence();                       // publish g_y4 writes
        atomicAdd(&g_bar1, 1u);
        while (*(volatile unsigned int*)&g_bar1 < gridDim.x) { }
        __threadfence();                       // acquire
    }
    __syncthreads();

    // ---------------- Phase 2: parallel deterministic reduction ----------------
    // g_y4 viewed as 4 slices of 12288 float4 each.
    {
        const float4* __restrict__ y4v = (const float4*)g_y4;
        const int total = (NVERT * 3) / 4;                       // 12288
        const int per   = (total + gridDim.x - 1) / gridDim.x;   // ~84
        const int base  = blockIdx.x * per;
        const int end   = (base + per < total) ? (base + per) : total;

        float s = 0.f;
        for (int i = base + threadIdx.x; i < end; i += BLOCK) {
            float4 a = y4v[i];
            float4 b = y4v[i + total];
            float4 c = y4v[i + 2 * total];
            float4 d = y4v[i + 3 * total];
            float vx = a.x + b.x + c.x + d.x;
            float vy = a.y + b.y + c.y + d.y;
            float vz = a.z + b.z + c.z + d.z;
            float vw = a.w + b.w + c.w + d.w;
            s += vx * vx + vy * vy + vz * vz + vw * vw;
        }
        float t = block_reduce(s, red);
        if (threadIdx.x == 0) {
            g_part[blockIdx.x] = t;
            __threadfence();
            atomicAdd(&g_bar2, 1u);
        }
    }

    // ---------------- Block 0 finalizes + resets state ----------------
    if (blockIdx.x == 0) {
        if (threadIdx.x == 0) {
            while (*(volatile unsigned int*)&g_bar2 < gridDim.x) { }
            __threadfence();
        }
        __syncthreads();

        float s = (threadIdx.x < gridDim.x) ? g_part[threadIdx.x] : 0.f;
        float t = block_reduce(s, red);
        if (threadIdx.x == 0) {
            out[0]   = t;
            g_ticket = 0;     // safe: every block has passed barrier 1 & 2
            g_bar1   = 0;
            g_bar2   = 0;
            __threadfence();
        }
    }
}

extern "C" void kernel_launch(void* const* d_in, const int* in_sizes, int n_in,
                              void* d_out, int out_size) {
    // Identify inputs by element count: x has NVERT*3, L has NVERT*NVERT.
    const float* x = (const float*)d_in[0];
    const float* L = (const float*)d_in[1];
    if (in_sizes[0] != NVERT * 3) {
        x = (const float*)d_in[1];
        L = (const float*)d_in[0];
    }
    float* out = (float*)d_out;

    // Grid = #SMs -> 1 resident CTA per SM (1024 thr + 192KB smem), making the
    // in-kernel grid spin-barrier deadlock-free on any SKU.
    int dev = 0;
    cudaGetDevice(&dev);
    int sms = 148;
    cudaDeviceGetAttribute(&sms, cudaDevAttrMultiProcessorCount, dev);
    if (sms < 1) sms = 1;
    if (sms > MAXGRID) sms = MAXGRID;

    cudaFuncSetAttribute(lap_fused_kernel,
                         cudaFuncAttributeMaxDynamicSharedMemorySize,
                         (int)SMEM_BYTES);

    lap_fused_kernel<<<sms, BLOCK, SMEM_BYTES>>>(L, x, out);
}